// round 2
// baseline (speedup 1.0000x reference)
#include <cuda_runtime.h>

#define NPIX  65536      // 64 * 32 * 32 pixels
#define KCODE 1024
#define DDIM  256
#define HW    1024       // 32*32, pixels per batch image

#define BM 128
#define BN 128
#define BK 16
#define BNS 132          // padded Bs row stride (store-conflict mitigation, keeps 16B align)

__device__ unsigned long long g_keys[NPIX];
__device__ float g_esq[KCODE];
__device__ float g_sf[NPIX];
__device__ float g_loss;

// ---------- helpers ----------
__device__ __forceinline__ unsigned f2ord(float f) {
    unsigned u = __float_as_uint(f);
    return (u & 0x80000000u) ? ~u : (u | 0x80000000u);
}
__device__ __forceinline__ unsigned long long pack_dup(float x) {
    unsigned long long r;
    asm("mov.b64 %0, {%1, %1};" : "=l"(r) : "f"(x));
    return r;
}
__device__ __forceinline__ void fma2(unsigned long long& d,
                                     unsigned long long a,
                                     unsigned long long b) {
    asm("fma.rn.f32x2 %0, %1, %2, %0;" : "+l"(d) : "l"(a), "l"(b));
}
__device__ __forceinline__ float2 unpack2(unsigned long long v) {
    float2 f;
    asm("mov.b64 {%0, %1}, %2;" : "=f"(f.x), "=f"(f.y) : "l"(v));
    return f;
}

// ---------- init: argmin keys to +inf, loss accumulator to 0 ----------
__global__ void k_init() {
    int i = blockIdx.x * 256 + threadIdx.x;
    g_keys[i] = ~0ULL;
    if (i == 0) g_loss = 0.f;
}

// ---------- ||e_k||^2, one warp per code row ----------
__global__ void k_esq(const float* __restrict__ emb) {
    int w    = (blockIdx.x * blockDim.x + threadIdx.x) >> 5;   // code id 0..1023
    int lane = threadIdx.x & 31;
    const float* row = emb + (size_t)w * DDIM;
    float s = 0.f;
#pragma unroll
    for (int j = 0; j < 8; ++j) { float v = row[lane + 32 * j]; s = fmaf(v, v, s); }
#pragma unroll
    for (int sh = 16; sh; sh >>= 1) s += __shfl_xor_sync(0xffffffffu, s, sh);
    if (lane == 0) g_esq[w] = s;
}

// ---------- ||f_n||^2, coalesced strided reduction over channels ----------
__global__ void k_sf(const float* __restrict__ lat) {
    int n = blockIdx.x * 256 + threadIdx.x;
    int b = n >> 10, p = n & 1023;
    const float* base = lat + (size_t)b * DDIM * HW + p;
    float s = 0.f;
#pragma unroll 4
    for (int d = 0; d < DDIM; ++d) { float v = base[(size_t)d * HW]; s = fmaf(v, v, s); }
    g_sf[n] = s;
}

// ---------- fused distance GEMM (f32x2 packed FMA) + argmin ----------
// Tile: 128 pixels x 128 codes, reduce over D=256 in BK=16 chunks.
// 256 threads, each owns an 8x8 micro-tile held as 8x4 packed f32x2 accumulators.
__global__ void __launch_bounds__(256, 2)
k_dist(const float* __restrict__ lat, const float* __restrict__ emb) {
    __shared__ __align__(16) float As[BK * BM];
    __shared__ __align__(16) float Bs[BK * BNS];

    const int tid = threadIdx.x;
    const int tx = tid & 15, ty = tid >> 4;
    const int n0 = blockIdx.x * BM;
    const int b  = n0 >> 10;
    const int p0 = n0 & 1023;
    const int c0 = blockIdx.y * BN;
    const float* Ab = lat + (size_t)b * DDIM * HW + p0;
    const float* Bb = emb + (size_t)c0 * DDIM;

    // load mappings (coalesced)
    const int aD = tid >> 5;          // 0..7   (d within chunk, two passes: aD, aD+8)
    const int aM = (tid & 31) << 2;   // 0..124 (pixel, float4)
    const int bN = tid >> 2;          // 0..63  (code, two passes: bN, bN+64)
    const int bD = (tid & 3) << 2;    // 0,4,8,12 (d, float4)

    unsigned long long acc[8][4];
#pragma unroll
    for (int i = 0; i < 8; ++i)
#pragma unroll
        for (int j = 0; j < 4; ++j) acc[i][j] = 0ULL;

    // register-staged prefetch
    float4 sa0 = *(const float4*)(Ab + (size_t)aD * HW + aM);
    float4 sa1 = *(const float4*)(Ab + (size_t)(aD + 8) * HW + aM);
    float4 sb0 = *(const float4*)(Bb + (size_t)bN * DDIM + bD);
    float4 sb1 = *(const float4*)(Bb + (size_t)(bN + 64) * DDIM + bD);

    for (int it = 0; it < DDIM / BK; ++it) {
        *(float4*)(As + aD * BM + aM)       = sa0;
        *(float4*)(As + (aD + 8) * BM + aM) = sa1;
        Bs[(bD + 0) * BNS + bN] = sb0.x;
        Bs[(bD + 1) * BNS + bN] = sb0.y;
        Bs[(bD + 2) * BNS + bN] = sb0.z;
        Bs[(bD + 3) * BNS + bN] = sb0.w;
        Bs[(bD + 0) * BNS + bN + 64] = sb1.x;
        Bs[(bD + 1) * BNS + bN + 64] = sb1.y;
        Bs[(bD + 2) * BNS + bN + 64] = sb1.z;
        Bs[(bD + 3) * BNS + bN + 64] = sb1.w;
        __syncthreads();
        if (it + 1 < DDIM / BK) {
            int d0 = (it + 1) * BK;
            sa0 = *(const float4*)(Ab + (size_t)(d0 + aD) * HW + aM);
            sa1 = *(const float4*)(Ab + (size_t)(d0 + aD + 8) * HW + aM);
            sb0 = *(const float4*)(Bb + (size_t)bN * DDIM + d0 + bD);
            sb1 = *(const float4*)(Bb + (size_t)(bN + 64) * DDIM + d0 + bD);
        }
#pragma unroll
        for (int d = 0; d < BK; ++d) {
            const float* ap = As + d * BM + (ty << 3);
            float4 a0 = *(const float4*)ap;
            float4 a1 = *(const float4*)(ap + 4);
            const double2* bp = (const double2*)(Bs + d * BNS + (tx << 3));
            double2 b01 = bp[0], b23 = bp[1];
            unsigned long long rn[4] = {
                __double_as_longlong(b01.x), __double_as_longlong(b01.y),
                __double_as_longlong(b23.x), __double_as_longlong(b23.y) };
            float am[8] = { a0.x, a0.y, a0.z, a0.w, a1.x, a1.y, a1.z, a1.w };
#pragma unroll
            for (int i = 0; i < 8; ++i) {
                unsigned long long rm = pack_dup(am[i]);
#pragma unroll
                for (int j = 0; j < 4; ++j) fma2(acc[i][j], rm, rn[j]);
            }
        }
        __syncthreads();
    }

    // epilogue: replicate reference rounding chain fl(fl(sf+se) - 2*dot),
    // pack (orderable(score), code) keys, per-row min, atomicMin merge.
#pragma unroll
    for (int i = 0; i < 8; ++i) {
        int row  = n0 + (ty << 3) + i;
        float sf = g_sf[row];
        unsigned long long best = ~0ULL;
#pragma unroll
        for (int j = 0; j < 4; ++j) {
            float2 dd = unpack2(acc[i][j]);
            int c = c0 + (tx << 3) + (j << 1);
            float t0 = sf + g_esq[c];          // fl(sf + se)  (matches ref broadcast-add)
            float t1 = sf + g_esq[c + 1];
            float s0 = fmaf(-2.f, dd.x, t0);   // == fl(t - 2*dot), 2*dot exact
            float s1 = fmaf(-2.f, dd.y, t1);
            unsigned long long k0 = ((unsigned long long)f2ord(s0) << 32) | (unsigned)c;
            unsigned long long k1 = ((unsigned long long)f2ord(s1) << 32) | (unsigned)(c + 1);
            if (k1 < k0) k0 = k1;
            if (k0 < best) best = k0;
        }
#pragma unroll
        for (int sh = 8; sh; sh >>= 1) {       // reduce across the 16 tx lanes (half-warp)
            unsigned long long o = __shfl_xor_sync(0xffffffffu, best, sh);
            if (o < best) best = o;
        }
        if (tx == 0) atomicMin(&g_keys[row], best);
    }
}

// ---------- gather + transposed write + fused MSE reduction ----------
// Each block: 32 pixels. Stage 32 codebook rows in smem, then write out[b,d,h,w]
// coalescing over pixels, accumulating sum((quant-lat)^2).
__global__ void k_gather(const float* __restrict__ lat, const float* __restrict__ emb,
                         float* __restrict__ out) {
    __shared__ __align__(16) float rows[32 * 260];
    __shared__ int sInd[32];
    const int t  = threadIdx.x;
    const int n0 = blockIdx.x << 5;
    const int b  = n0 >> 10, p0 = n0 & 1023;

    if (t < 32) sInd[t] = (int)(unsigned)(g_keys[n0 + t]);   // low 32 bits = code index
    __syncthreads();
#pragma unroll
    for (int i = 0; i < 8; ++i) {
        int idx4 = t + (i << 8);
        int r = idx4 >> 6, c4 = (idx4 & 63) << 2;
        float4 v = *(const float4*)(emb + (size_t)sInd[r] * DDIM + c4);
        *(float4*)(rows + r * 260 + c4) = v;
    }
    __syncthreads();

    const int i = t & 31, db = t >> 5;
    float accl = 0.f;
#pragma unroll
    for (int dd = 0; dd < 32; ++dd) {
        int d = (dd << 3) + db;
        size_t gi = ((size_t)(b * DDIM + d)) * HW + p0 + i;
        float q = rows[i * 260 + d];
        float l = lat[gi];
        out[gi] = q;                      // straight-through output == quant
        float df = q - l;
        accl = fmaf(df, df, accl);
    }
#pragma unroll
    for (int sh = 16; sh; sh >>= 1) accl += __shfl_xor_sync(0xffffffffu, accl, sh);
    if ((t & 31) == 0) atomicAdd(&g_loss, accl);
}

// ---------- scalars ----------
__global__ void k_final(float* __restrict__ out, int off) {
    float S = g_loss * (1.0f / 16777216.0f);   // mean over N*D elements
    out[off]     = S;          // embedding_loss
    out[off + 1] = 0.25f * S;  // BETA * commitment_loss (numerically identical mean)
}

extern "C" void kernel_launch(void* const* d_in, const int* in_sizes, int n_in,
                              void* d_out, int out_size) {
    const float* lat = (const float*)d_in[0];   // latents [64,256,32,32]
    const float* emb = (const float*)d_in[1];   // embedding [1024,256]
    float* out = (float*)d_out;

    k_init<<<NPIX / 256, 256>>>();
    k_esq<<<KCODE / 8, 256>>>(emb);
    k_sf<<<NPIX / 256, 256>>>(lat);
    k_dist<<<dim3(NPIX / BM, KCODE / BN), 256>>>(lat, emb);
    k_gather<<<NPIX / 32, 256>>>(lat, emb, out);
    if (out_size >= NPIX * DDIM + 2) {
        k_final<<<1, 1>>>(out, out_size - 2);
    }
}

// round 4
// speedup vs baseline: 1.7405x; 1.7405x over previous
#include <cuda_runtime.h>
#include <cuda_bf16.h>
#include <cuda_fp16.h>
#include <cstdint>

#define NPIX  65536
#define KCODE 1024
#define DDIM  256
#define HW    1024
#define MARGIN 1e-3f

// ---------------- device scratch (static; no allocs) ----------------
// blocked bf16 tiles: [tile][kiter] -> 8KB block of 128 rows x 64B, swizzled
__device__ __align__(128) unsigned char F_tiles[(size_t)512 * 8 * 8192];  // 32MB
__device__ __align__(128) unsigned char E_tiles[(size_t)8 * 8 * 8192];    // 512KB
__device__ __align__(128) __half2 g_dots[(size_t)NPIX * KCODE / 2];       // 128MB
__device__ unsigned long long g_keys[NPIX];
__device__ float g_esq[KCODE];
__device__ float g_sf[NPIX];
__device__ float g_loss;

// ---------------- helpers ----------------
__device__ __forceinline__ unsigned f2ord(float f) {
    unsigned u = __float_as_uint(f);
    return (u & 0x80000000u) ? ~u : (u | 0x80000000u);
}
__device__ __forceinline__ uint32_t smem_u32(const void* p) {
    uint32_t a;
    asm("{ .reg .u64 t; cvta.to.shared.u64 t, %1; cvt.u32.u64 %0, t; }" : "=r"(a) : "l"(p));
    return a;
}
__device__ __forceinline__ uint32_t bf2(float a, float b) {
    __nv_bfloat162 h = __float22bfloat162_rn(make_float2(a, b));
    return *reinterpret_cast<uint32_t*>(&h);
}
#define SWZ64(off) ((off) ^ (((off) >> 3) & 0x30u))

#define MBAR_INIT(mb, cnt) \
    asm volatile("mbarrier.init.shared.b64 [%0], %1;" :: "r"(mb), "r"((uint32_t)(cnt)) : "memory")
#define MBAR_EXPECT(mb, tx) \
    asm volatile("mbarrier.arrive.expect_tx.shared.b64 _, [%0], %1;" :: "r"(mb), "r"((uint32_t)(tx)) : "memory")
#define MBAR_WAIT(mb, ph) do {                                                          \
    uint32_t _m = (mb), _p = (ph), _d;                                                  \
    asm volatile("{\n\t.reg .pred p;\n\t"                                               \
        "mbarrier.try_wait.parity.acquire.cta.shared::cta.b64 p, [%1], %2;\n\t"         \
        "selp.b32 %0, 1, 0, p;\n\t}" : "=r"(_d) : "r"(_m), "r"(_p) : "memory");         \
    if (!_d) {                                                                           \
        asm volatile("{\n\t.reg .pred P1;\n\t"                                           \
            "W_%=:\n\t"                                                                  \
            "mbarrier.try_wait.parity.acquire.cta.shared::cta.b64 P1, [%0], %1, 0x989680;\n\t" \
            "@P1 bra.uni D_%=;\n\t"                                                      \
            "bra.uni W_%=;\n\t"                                                          \
            "D_%=:\n\t}" :: "r"(_m), "r"(_p) : "memory");                                \
    }                                                                                    \
} while (0)

__device__ __forceinline__ void bulk_g2s(uint32_t dst, const void* src, uint32_t bytes, uint32_t mb) {
    asm volatile("cp.async.bulk.shared::cta.global.mbarrier::complete_tx::bytes [%0], [%1], %2, [%3];"
                 :: "r"(dst), "l"(src), "r"(bytes), "r"(mb) : "memory");
}
__device__ __forceinline__ void ldsm4(uint32_t* r, uint32_t addr) {
    asm volatile("ldmatrix.sync.aligned.m8n8.x4.shared.b16 {%0,%1,%2,%3}, [%4];"
                 : "=r"(r[0]), "=r"(r[1]), "=r"(r[2]), "=r"(r[3]) : "r"(addr));
}
__device__ __forceinline__ void mma16816(float* c, const uint32_t* a, uint32_t b0, uint32_t b1) {
    asm volatile("mma.sync.aligned.m16n8k16.row.col.f32.bf16.bf16.f32 "
                 "{%0,%1,%2,%3}, {%4,%5,%6,%7}, {%8,%9}, {%0,%1,%2,%3};"
                 : "+f"(c[0]), "+f"(c[1]), "+f"(c[2]), "+f"(c[3])
                 : "r"(a[0]), "r"(a[1]), "r"(a[2]), "r"(a[3]), "r"(b0), "r"(b1));
}

// ---------------- small kernels ----------------
__global__ void k_zero() { if (threadIdx.x == 0) g_loss = 0.f; }

// ||e_k||^2 — identical chain to round-1 passing kernel
__global__ void k_esq(const float* __restrict__ emb) {
    int w    = (blockIdx.x * blockDim.x + threadIdx.x) >> 5;
    int lane = threadIdx.x & 31;
    const float* row = emb + (size_t)w * DDIM;
    float s = 0.f;
#pragma unroll
    for (int j = 0; j < 8; ++j) { float v = row[lane + 32 * j]; s = fmaf(v, v, s); }
#pragma unroll
    for (int sh = 16; sh; sh >>= 1) s += __shfl_xor_sync(0xffffffffu, s, sh);
    if (lane == 0) g_esq[w] = s;
}

// ||f_n||^2 — unchanged from round 1
__global__ void k_sf(const float* __restrict__ lat) {
    int n = blockIdx.x * 256 + threadIdx.x;
    int b = n >> 10, p = n & 1023;
    const float* base = lat + (size_t)b * DDIM * HW + p;
    float s = 0.f;
#pragma unroll 4
    for (int d = 0; d < DDIM; ++d) { float v = base[(size_t)d * HW]; s = fmaf(v, v, s); }
    g_sf[n] = s;
}

// embedding -> blocked swizzled bf16 tiles. grid (8 cblk, 8 kiter), 256 thr.
__global__ void k_prep_emb(const float* __restrict__ emb) {
    int c0 = blockIdx.x << 7, d0 = blockIdx.y << 5;
    unsigned char* dst = E_tiles + ((size_t)(blockIdx.x * 8 + blockIdx.y)) * 8192;
    int t = threadIdx.x;
#pragma unroll
    for (int i = 0; i < 2; ++i) {
        int u = t + (i << 8);                 // 512 16B units
        int r = u >> 2, c8 = (u & 3) << 3;    // code row, 8 k's
        const float* src = emb + (size_t)(c0 + r) * DDIM + d0 + c8;
        float4 v0 = *(const float4*)src;
        float4 v1 = *(const float4*)(src + 4);
        uint4 o;
        o.x = bf2(v0.x, v0.y); o.y = bf2(v0.z, v0.w);
        o.z = bf2(v1.x, v1.y); o.w = bf2(v1.z, v1.w);
        *(uint4*)(dst + SWZ64((uint32_t)(u << 4))) = o;
    }
}

// latents -> transposed blocked swizzled bf16 tiles. grid (512 tiles, 8 kiter).
__global__ void k_prep_lat(const float* __restrict__ lat) {
    __shared__ float ts[32][129];
    int tile = blockIdx.x, kit = blockIdx.y;
    int b = tile >> 3, p0 = (tile & 7) << 7, d0 = kit << 5;
    int t = threadIdx.x;
#pragma unroll
    for (int i = 0; i < 4; ++i) {
        int u = t + (i << 8);                 // 1024 float4 units (32 rows x 32)
        int r = u >> 5, c4 = (u & 31) << 2;
        float4 v = *(const float4*)(lat + (((size_t)(b * 256 + d0 + r)) << 10) + p0 + c4);
        ts[r][c4] = v.x; ts[r][c4 + 1] = v.y; ts[r][c4 + 2] = v.z; ts[r][c4 + 3] = v.w;
    }
    __syncthreads();
    unsigned char* dst = F_tiles + ((size_t)(tile * 8 + kit)) * 8192;
#pragma unroll
    for (int i = 0; i < 2; ++i) {
        int u = t + (i << 8);                 // 512 16B units
        int p = u >> 2, c8 = (u & 3) << 3;    // pixel row, 8 d's
        uint4 o;
        o.x = bf2(ts[c8][p],     ts[c8 + 1][p]);
        o.y = bf2(ts[c8 + 2][p], ts[c8 + 3][p]);
        o.z = bf2(ts[c8 + 4][p], ts[c8 + 5][p]);
        o.w = bf2(ts[c8 + 6][p], ts[c8 + 7][p]);
        *(uint4*)(dst + SWZ64((uint32_t)(u << 4))) = o;
    }
}

// ---------------- HMMA distance GEMM -> fp16 dot dump ----------------
// 128 pixels x 128 codes per CTA, K=256 in 8 chunks of 32, double-buffered bulk copies.
__global__ void __launch_bounds__(256, 2)
k_dist() {
    __shared__ __align__(128) unsigned char buf[2][16384];
    __shared__ __align__(8) unsigned long long bar[2];

    const int tid = threadIdx.x;
    const int lane = tid & 31, wid = tid >> 5;
    const int tile = blockIdx.x, cblk = blockIdx.y;
    const int pix0 = tile << 7, n0 = cblk << 7;
    const int wm = (wid & 3) << 5, wn = (wid >> 2) << 6;
    const int rl = lane & 15, ch = (lane >> 4) << 4;

    if (tid == 0) { MBAR_INIT(smem_u32(&bar[0]), 1); MBAR_INIT(smem_u32(&bar[1]), 1); }
    __syncthreads();
    if (tid == 0) {
#pragma unroll
        for (int s = 0; s < 2; ++s) {
            uint32_t mb = smem_u32(&bar[s]);
            MBAR_EXPECT(mb, 16384);
            bulk_g2s(smem_u32(buf[s]),         F_tiles + ((size_t)(tile * 8 + s)) * 8192, 8192, mb);
            bulk_g2s(smem_u32(buf[s]) + 8192,  E_tiles + ((size_t)(cblk * 8 + s)) * 8192, 8192, mb);
        }
    }

    float acc[2][8][4];
#pragma unroll
    for (int i = 0; i < 2; ++i)
#pragma unroll
        for (int j = 0; j < 8; ++j)
#pragma unroll
            for (int q = 0; q < 4; ++q) acc[i][j][q] = 0.f;

    for (int k = 0; k < 8; ++k) {
        const int bs = k & 1;
        MBAR_WAIT(smem_u32(&bar[bs]), (k >> 1) & 1);
        uint32_t As = smem_u32(buf[bs]);
        uint32_t Bs = As + 8192;
#pragma unroll
        for (int s = 0; s < 2; ++s) {
            const uint32_t cb = (s << 5) + ch;
            uint32_t af[2][4], bf[4][4];
#pragma unroll
            for (int i = 0; i < 2; ++i)
                ldsm4(af[i], As + SWZ64((uint32_t)(((wm + (i << 4) + rl) << 6) + cb)));
#pragma unroll
            for (int j = 0; j < 4; ++j)
                ldsm4(bf[j], Bs + SWZ64((uint32_t)(((wn + (j << 4) + rl) << 6) + cb)));
#pragma unroll
            for (int i = 0; i < 2; ++i)
#pragma unroll
                for (int j = 0; j < 4; ++j) {
                    mma16816(acc[i][2 * j],     af[i], bf[j][0], bf[j][2]);
                    mma16816(acc[i][2 * j + 1], af[i], bf[j][1], bf[j][3]);
                }
        }
        __syncthreads();
        if (tid == 0 && k < 6) {
            uint32_t mb = smem_u32(&bar[bs]);
            MBAR_EXPECT(mb, 16384);
            bulk_g2s(smem_u32(buf[bs]),        F_tiles + ((size_t)(tile * 8 + k + 2)) * 8192, 8192, mb);
            bulk_g2s(smem_u32(buf[bs]) + 8192, E_tiles + ((size_t)(cblk * 8 + k + 2)) * 8192, 8192, mb);
        }
    }

    // dump dots as fp16 pairs
    const int g = lane >> 2, tg = lane & 3;
#pragma unroll
    for (int i = 0; i < 2; ++i) {
        int pixA = pix0 + wm + (i << 4) + g;
        int codp = (n0 + wn + (tg << 1)) >> 1;        // half2 column index base
#pragma unroll
        for (int j = 0; j < 8; ++j) {
            int cidx = codp + (j << 2);               // + jj*8/2
            g_dots[((size_t)pixA << 9) + cidx] =
                __float22half2_rn(make_float2(acc[i][j][0], acc[i][j][1]));
            g_dots[((size_t)(pixA + 8) << 9) + cidx] =
                __float22half2_rn(make_float2(acc[i][j][2], acc[i][j][3]));
        }
    }
}

// ---------------- selection: approx min + exact rescore ----------------
// block = 32 pixels, 256 threads (8 threads per pixel, 128 codes each)
__global__ void __launch_bounds__(256, 1)
k_select(const float* __restrict__ lat, const float* __restrict__ emb) {
    __shared__ float sm_f[256][33];     // latent columns, exact fp32
    __shared__ float esq_p[1024];       // permuted: [(c&127)<<3 | c>>7]

    const int t = threadIdx.x;
    const int p0g = blockIdx.x << 5;
    const int b = p0g >> 10, p0 = p0g & 1023;

#pragma unroll
    for (int i = 0; i < 4; ++i) {
        int c = t + (i << 8);
        esq_p[((c & 127) << 3) | (c >> 7)] = g_esq[c];
    }
#pragma unroll
    for (int i = 0; i < 32; ++i) {
        int d = (i << 3) + (t >> 5), px = t & 31;
        sm_f[d][px] = lat[(((size_t)(b * 256 + d)) << 10) + p0 + px];
    }
    __syncthreads();

    const int px = t >> 3, tg = t & 7;
    const int pix = p0g + px;
    const float sf = g_sf[pix];
    const uint4* dot4 = reinterpret_cast<const uint4*>(g_dots) + ((size_t)pix << 7) + (tg << 4);

    // pass 1: approximate min
    float mn = __int_as_float(0x7f800000);
#pragma unroll 4
    for (int j = 0; j < 16; ++j) {
        uint4 v = dot4[j];
        const uint32_t w[4] = { v.x, v.y, v.z, v.w };
#pragma unroll
        for (int q = 0; q < 4; ++q) {
            float2 dd = __half22float2(*reinterpret_cast<const __half2*>(&w[q]));
            int i0 = (j << 3) + (q << 1);
            float s0 = fmaf(-2.f, dd.x, sf + esq_p[(i0 << 3) | tg]);
            float s1 = fmaf(-2.f, dd.y, sf + esq_p[((i0 + 1) << 3) | tg]);
            mn = fminf(mn, fminf(s0, s1));
        }
    }
#pragma unroll
    for (int sh = 4; sh; sh >>= 1) mn = fminf(mn, __shfl_xor_sync(0xffffffffu, mn, sh));
    const float thr = mn + MARGIN;

    // pass 2: exact rescore of candidates
    unsigned long long best = ~0ULL;
#pragma unroll 2
    for (int j = 0; j < 16; ++j) {
        uint4 v = dot4[j];
        const uint32_t w[4] = { v.x, v.y, v.z, v.w };
#pragma unroll
        for (int q = 0; q < 4; ++q) {
            float2 dd = __half22float2(*reinterpret_cast<const __half2*>(&w[q]));
#pragma unroll
            for (int e = 0; e < 2; ++e) {
                int i0 = (j << 3) + (q << 1) + e;
                float ap = fmaf(-2.f, e ? dd.y : dd.x, sf + esq_p[(i0 << 3) | tg]);
                if (ap <= thr) {
                    int code = (tg << 7) + i0;
                    const float4* er = reinterpret_cast<const float4*>(emb + ((size_t)code << 8));
                    float a0 = 0.f, a1 = 0.f, a2 = 0.f, a3 = 0.f;
#pragma unroll 8
                    for (int d4 = 0; d4 < 64; ++d4) {
                        float4 e4 = __ldg(er + d4);
                        int d = d4 << 2;
                        a0 = fmaf(sm_f[d][px],     e4.x, a0);
                        a1 = fmaf(sm_f[d + 1][px], e4.y, a1);
                        a2 = fmaf(sm_f[d + 2][px], e4.z, a2);
                        a3 = fmaf(sm_f[d + 3][px], e4.w, a3);
                    }
                    float dot = (a0 + a1) + (a2 + a3);
                    float sx = fmaf(-2.f, dot, sf + esq_p[(i0 << 3) | tg]);  // exact chain
                    unsigned long long key = ((unsigned long long)f2ord(sx) << 32) | (unsigned)code;
                    if (key < best) best = key;
                }
            }
        }
    }
#pragma unroll
    for (int sh = 4; sh; sh >>= 1) {
        unsigned long long o = __shfl_xor_sync(0xffffffffu, best, sh);
        if (o < best) best = o;
    }
    if (tg == 0) g_keys[pix] = best;
}

// ---------------- gather + transposed write + fused MSE (unchanged, R1-verified) ----------------
__global__ void k_gather(const float* __restrict__ lat, const float* __restrict__ emb,
                         float* __restrict__ out) {
    __shared__ __align__(16) float rows[32 * 260];
    __shared__ int sInd[32];
    const int t  = threadIdx.x;
    const int n0 = blockIdx.x << 5;
    const int b  = n0 >> 10, p0 = n0 & 1023;

    if (t < 32) sInd[t] = (int)(unsigned)(g_keys[n0 + t]);
    __syncthreads();
#pragma unroll
    for (int i = 0; i < 8; ++i) {
        int idx4 = t + (i << 8);
        int r = idx4 >> 6, c4 = (idx4 & 63) << 2;
        float4 v = *(const float4*)(emb + (size_t)sInd[r] * DDIM + c4);
        *(float4*)(rows + r * 260 + c4) = v;
    }
    __syncthreads();

    const int i = t & 31, db = t >> 5;
    float accl = 0.f;
#pragma unroll
    for (int dd = 0; dd < 32; ++dd) {
        int d = (dd << 3) + db;
        size_t gi = ((size_t)(b * DDIM + d)) * HW + p0 + i;
        float q = rows[i * 260 + d];
        float l = lat[gi];
        out[gi] = q;
        float df = q - l;
        accl = fmaf(df, df, accl);
    }
#pragma unroll
    for (int sh = 16; sh; sh >>= 1) accl += __shfl_xor_sync(0xffffffffu, accl, sh);
    if ((t & 31) == 0) atomicAdd(&g_loss, accl);
}

__global__ void k_final(float* __restrict__ out, int off) {
    float S = g_loss * (1.0f / 16777216.0f);
    out[off]     = S;
    out[off + 1] = 0.25f * S;
}

extern "C" void kernel_launch(void* const* d_in, const int* in_sizes, int n_in,
                              void* d_out, int out_size) {
    const float* lat = (const float*)d_in[0];
    const float* emb = (const float*)d_in[1];
    float* out = (float*)d_out;

    k_zero<<<1, 32>>>();
    k_esq<<<KCODE / 8, 256>>>(emb);
    k_sf<<<NPIX / 256, 256>>>(lat);
    k_prep_emb<<<dim3(8, 8), 256>>>(emb);
    k_prep_lat<<<dim3(512, 8), 256>>>(lat);
    k_dist<<<dim3(512, 8), 256>>>();
    k_select<<<NPIX / 32, 256>>>(lat, emb);
    k_gather<<<NPIX / 32, 256>>>(lat, emb, out);
    if (out_size >= NPIX * DDIM + 2) {
        k_final<<<1, 1>>>(out, out_size - 2);
    }
}